// round 13
// baseline (speedup 1.0000x reference)
#include <cuda_runtime.h>
#include <cfloat>

#define Bn 512
#define Tn 512
#define Kn 64
#define PD 8  // potentials prefetch ring depth (registers)

__device__ int g_seq[Bn];

// Monotone float <-> uint order-preserving map (finite floats).
__device__ __forceinline__ unsigned fmap(float f) {
    const int i = __float_as_int(f);
    return (unsigned)(i ^ ((i >> 31) | 0x80000000));
}
__device__ __forceinline__ float funmap(unsigned u) {
    const int s = ~((int)u >> 31);
    return __int_as_float((int)(u ^ (0x80000000u | (unsigned)s)));
}

// Predicated shared stores (inline PTX: @p stores, no BSSY reconvergence frames)
__device__ __forceinline__ void sts_init4(unsigned addr, float ninf, int pred) {
    asm volatile(
        "{ .reg .pred p; setp.ne.b32 p, %2, 0; @p st.shared.v4.f32 [%0], {%1,%1,%1,%1}; }"
        :: "r"(addr), "f"(ninf), "r"(pred) : "memory");
}
__device__ __forceinline__ void sts_f32_pred(unsigned addr, float v, int pred) {
    asm volatile(
        "{ .reg .pred p; setp.ne.b32 p, %2, 0; @p st.shared.f32 [%0], %1; }"
        :: "r"(addr), "f"(v), "r"(pred) : "memory");
}
__device__ __forceinline__ void sts_u8_pred(unsigned addr, unsigned v, int pred) {
    asm volatile(
        "{ .reg .pred p; setp.ne.b32 p, %2, 0; @p st.shared.u8 [%0], %1; }"
        :: "r"(addr), "r"(v), "r"(pred) : "memory");
}

// ---------------------------------------------------------------------------
// Kernel 1: seq_lens[b] = int( mean_k( sum_t (x[b,t,k] != 0) ) )  (exact)
// ---------------------------------------------------------------------------
__global__ __launch_bounds__(256) void seqlen_kernel(const float* __restrict__ x) {
    __shared__ int red[256];
    const int b = blockIdx.x;
    const float4* xb = (const float4*)(x + (size_t)b * Tn * Kn);
    int c = 0;
    for (int i = threadIdx.x; i < (Tn * Kn) / 4; i += 256) {
        float4 v = xb[i];
        c += (v.x != 0.0f) + (v.y != 0.0f) + (v.z != 0.0f) + (v.w != 0.0f);
    }
    red[threadIdx.x] = c;
    __syncthreads();
    for (int s = 128; s > 0; s >>= 1) {
        if (threadIdx.x < s) red[threadIdx.x] += red[threadIdx.x + s];
        __syncthreads();
    }
    if (threadIdx.x == 0) g_seq[b] = red[0] >> 6;  // floor(total / 64)
}

// ---------------------------------------------------------------------------
// Exact full 64-candidate scan (fallback / general path). First max wins.
// ---------------------------------------------------------------------------
__device__ __noinline__ void full_scan64(
    float a_lo, float a_hi, const float2* trans2, int l,
    float& best0, float& best1, int& bi0, int& bi1)
{
    float b0 = -FLT_MAX, b1 = -FLT_MAX;
    int x0 = 0, x1 = 0;
#pragma unroll 4
    for (int i = 0; i < Kn; i++) {
        const float asel = (i < 32) ? a_lo : a_hi;
        const float av = __shfl_sync(0xffffffffu, asel, i & 31);
        const float2 tv = trans2[i * 32 + l];
        const float s0 = av + tv.x, s1 = av + tv.y;
        const bool g0 = s0 > b0; b0 = g0 ? s0 : b0; x0 = g0 ? i : x0;
        const bool g1 = s1 > b1; b1 = g1 ? s1 : b1; x1 = g1 ? i : x1;
    }
    best0 = b0; best1 = b1; bi0 = x0; bi1 = x1;
}

// End-of-step candidate prep: exact threshold, ballot, rank, smem deposit.
// (All excluded tags lose STRICTLY for every to-tag -> pruning is exact.)
#define PREP_CAND()                                                          \
    {                                                                        \
        const float fm_ = fmaxf(a_lo, a_hi);                                 \
        const unsigned wm_ = __reduce_max_sync(0xffffffffu, fmap(fm_));      \
        const float thr_ = funmap(wm_) - rTp;                                \
        const int pl_ = (a_lo >= thr_);                                      \
        const int ph_ = (a_hi >= thr_);                                      \
        const unsigned mlo_ = __ballot_sync(0xffffffffu, pl_ != 0);          \
        const unsigned mhi_ = __ballot_sync(0xffffffffu, ph_ != 0);          \
        const int nlo_ = __popc(mlo_);                                       \
        Cc = nlo_ + __popc(mhi_);                                            \
        const int rlo_ = __popc(mlo_ & lmlt);                                \
        const int rhi_ = nlo_ + __popc(mhi_ & lmlt);                         \
        sts_init4(cv_addr, NINF, is_l0);  /* lane0 resets value slots */     \
        sts_f32_pred(cv_addr + rlo_ * 4, a_lo, pl_ & (rlo_ < 4));            \
        sts_u8_pred(ci_addr + rlo_, (unsigned)l, pl_ & (rlo_ < 4));          \
        sts_f32_pred(cv_addr + rhi_ * 4, a_hi, ph_ & (rhi_ < 4));            \
        sts_u8_pred(ci_addr + rhi_, (unsigned)(32 + l), ph_ & (rhi_ < 4));   \
        __syncwarp();                                                        \
    }

// One DP step (fast path, t < sl guaranteed). Ring slot S_ is compile-time.
// Gathers the <=4 deposited candidates via ONE LDS.128 + ONE LDS.32 (vs
// 4x ffsll + 4x SHFL in R10). Stale slots hold -inf (never match best);
// stale tag bytes masked &63 (bounded smem access). C>4 -> exact fallback.
#define STEP_F(T_, S_)                                                       \
    {                                                                        \
        const int t_ = (T_);                                                 \
        const float p_lo = plo[S_];                                          \
        const float p_hi = phi[S_];                                          \
        {                                                                    \
            const int tl_ = (t_ + PD <= Tn - 1) ? (t_ + PD) : (Tn - 1);      \
            plo[S_] = pb[tl_ * Kn + l];                                      \
            phi[S_] = pb[tl_ * Kn + 32 + l];                                 \
        }                                                                    \
        const float4 cv_ = *(const float4*)cand_v;   /* LDS.128 broadcast */ \
        const unsigned iw_ = cand_i;                 /* LDS.32  broadcast */ \
        const int i0 = (int)(iw_ & 63u);                                     \
        const int i1 = (int)((iw_ >> 8) & 63u);                              \
        const int i2 = (int)((iw_ >> 16) & 63u);                             \
        const int i3 = (int)((iw_ >> 24) & 63u);                             \
        const float2 tv0 = trans2[i0 * 32 + l];                              \
        const float2 tv1 = trans2[i1 * 32 + l];                              \
        const float2 tv2 = trans2[i2 * 32 + l];                              \
        const float2 tv3 = trans2[i3 * 32 + l];                              \
        const float sa0 = cv_.x + tv0.x, sb0 = cv_.x + tv0.y;                \
        const float sa1 = cv_.y + tv1.x, sb1 = cv_.y + tv1.y;                \
        const float sa2 = cv_.z + tv2.x, sb2 = cv_.z + tv2.y;                \
        const float sa3 = cv_.w + tv3.x, sb3 = cv_.w + tv3.y;                \
        float best0 = fmaxf(fmaxf(sa0, sa1), fmaxf(sa2, sa3));               \
        float best1 = fmaxf(fmaxf(sb0, sb1), fmaxf(sb2, sb3));               \
        /* recovery: slots are ascending-tag; slot0 applied last ->          \
           smallest tag among value-ties wins == jnp.argmax (exact) */       \
        int bi0 = i3, bi1 = i3;                                              \
        bi0 = (sa2 == best0) ? i2 : bi0;  bi1 = (sb2 == best1) ? i2 : bi1;   \
        bi0 = (sa1 == best0) ? i1 : bi0;  bi1 = (sb1 == best1) ? i1 : bi1;   \
        bi0 = (sa0 == best0) ? i0 : bi0;  bi1 = (sb0 == best1) ? i0 : bi1;   \
        if (Cc > 4)  /* rare: exact full rescan from prev alpha (regs) */    \
            full_scan64(a_lo, a_hi, trans2, l, best0, best1, bi0, bi1);      \
        a_lo = p_lo + best0;                                                 \
        a_hi = p_hi + best1;                                                 \
        bp16[(t_ - 1) * 32 + l] =                                            \
            (unsigned short)((unsigned)bi0 | ((unsigned)bi1 << 8));          \
        PREP_CAND();                                                         \
    }

// ---------------------------------------------------------------------------
// Kernel 2: single-warp Viterbi, exact-threshold pruned step with smem
// candidate compaction.
// ---------------------------------------------------------------------------
__global__ __launch_bounds__(32) void viterbi_kernel(
    const float* __restrict__ pots,   // [B, T, K]
    const float* __restrict__ trans,  // [K, K]
    float* __restrict__ out)          // [B, T] float32
{
    extern __shared__ float2 trans2[];              // [64][32]: (T[i][l], T[i][l+32])
    __shared__ unsigned short bp16[(Tn - 1) * 32];  // packed (bi0 | bi1<<8)
    __shared__ unsigned char tags[Tn];
    __shared__ float alpha_f[Kn];
    __shared__ __align__(16) float cand_v[4];       // candidate alpha values
    __shared__ unsigned cand_i;                     // candidate tags (4 bytes)

    const int b = blockIdx.x;
    const int l = threadIdx.x;  // lane; owns to-tags l and l+32

    // ---- Prologue: stage transitions (float2-packed) + padded range ----
    const float4* tr4 = (const float4*)trans;
    float tmin = FLT_MAX, tmax = -FLT_MAX;
#pragma unroll
    for (int q = 0; q < 32; q++) {
        const int idx = q * 32 + l;
        const float4 v = tr4[idx];
        tmin = fminf(tmin, fminf(fminf(v.x, v.y), fminf(v.z, v.w)));
        tmax = fmaxf(tmax, fmaxf(fmaxf(v.x, v.y), fmaxf(v.z, v.w)));
        const int base = idx * 4;
        const int i = base >> 6;
        const int c = base & 63;
        if (c < 32) {
            trans2[i * 32 + c + 0].x = v.x;
            trans2[i * 32 + c + 1].x = v.y;
            trans2[i * 32 + c + 2].x = v.z;
            trans2[i * 32 + c + 3].x = v.w;
        } else {
            const int cc = c - 32;
            trans2[i * 32 + cc + 0].y = v.x;
            trans2[i * 32 + cc + 1].y = v.y;
            trans2[i * 32 + cc + 2].y = v.z;
            trans2[i * 32 + cc + 3].y = v.w;
        }
    }
    const unsigned rmn = __reduce_min_sync(0xffffffffu, fmap(tmin));
    const unsigned rmx = __reduce_max_sync(0xffffffffu, fmap(tmax));
    const float r = funmap(rmx) - funmap(rmn);
    const float rTp = r + fabsf(r) * 1e-5f + 0.01f;  // pad only ADDS candidates
    __syncwarp();

    const float* pb = pots + (size_t)b * Tn * Kn;
    int sl = g_seq[b];
    if (sl > Tn) sl = Tn;

    float a_lo = pb[l];
    float a_hi = pb[32 + l];

    if (sl >= Tn) {
        // ---------------- FAST PATH: every step active ----------------------
        const unsigned lmlt = (1u << l) - 1u;
        const unsigned cv_addr = (unsigned)__cvta_generic_to_shared(cand_v);
        const unsigned ci_addr = (unsigned)__cvta_generic_to_shared(&cand_i);
        const int is_l0 = (l == 0);
        const float NINF = -FLT_MAX;
        int Cc;

        if (l == 0) cand_i = 0;  // bound stale tag bytes once
        __syncwarp();
        PREP_CAND();             // deposits candidates from alpha0

        float plo[PD], phi[PD];
#pragma unroll
        for (int d = 1; d <= PD; d++) {
            plo[d & (PD - 1)] = pb[d * Kn + l];
            phi[d & (PD - 1)] = pb[d * Kn + 32 + l];
        }
        int t = 1;
#pragma unroll 1
        for (int tb = 0; tb < 63; tb++) {
            STEP_F(t + 0, 1); STEP_F(t + 1, 2); STEP_F(t + 2, 3); STEP_F(t + 3, 4);
            STEP_F(t + 4, 5); STEP_F(t + 5, 6); STEP_F(t + 6, 7); STEP_F(t + 7, 0);
            t += 8;
        }
        STEP_F(t + 0, 1); STEP_F(t + 1, 2); STEP_F(t + 2, 3); STEP_F(t + 3, 4);
        STEP_F(t + 4, 5); STEP_F(t + 5, 6); STEP_F(t + 6, 7);
    } else {
        // ---------------- GENERAL PATH (rare): exact full scan ---------------
#pragma unroll 1
        for (int t = 1; t < Tn; t++) {
            if (t < sl) {
                float best0, best1; int bi0, bi1;
                full_scan64(a_lo, a_hi, trans2, l, best0, best1, bi0, bi1);
                a_lo = pb[t * Kn + l] + best0;
                a_hi = pb[t * Kn + 32 + l] + best1;
                bp16[(t - 1) * 32 + l] =
                    (unsigned short)((unsigned)bi0 | ((unsigned)bi1 << 8));
            } else {
                bp16[(t - 1) * 32 + l] =
                    (unsigned short)((unsigned)l | ((unsigned)(32 + l) << 8));
            }
        }
    }

    // Final alpha -> smem for the backtrace scan
    alpha_f[l] = a_lo;
    alpha_f[32 + l] = a_hi;
    __syncwarp();

    // Backtrace (smem pointer-chase) by lane 0. First max wins.
    if (l == 0) {
        float bv = alpha_f[0];
        int bt = 0;
#pragma unroll 1
        for (int i = 1; i < Kn; i++) {
            const float v = alpha_f[i];
            if (v > bv) { bv = v; bt = i; }
        }
        int tg = bt;
        tags[Tn - 1] = (unsigned char)tg;
#pragma unroll 1
        for (int tt = Tn - 2; tt >= 0; tt--) {
            const unsigned v = bp16[tt * 32 + (tg & 31)];
            tg = (int)((v >> ((tg >> 5) * 8)) & 0xffu);
            tags[tt] = (unsigned char)tg;
        }
    }
    __syncwarp();

    // Coalesced float32 output write (16 per lane).
    float* ob = out + (size_t)b * Tn;
#pragma unroll
    for (int tt = l; tt < Tn; tt += 32) ob[tt] = (float)tags[tt];
}

// ---------------------------------------------------------------------------
extern "C" void kernel_launch(void* const* d_in, const int* in_sizes, int n_in,
                              void* d_out, int out_size) {
    const float* inputs = nullptr;
    const float* transitions = nullptr;
    for (int i = 0; i < n_in; i++) {
        if (in_sizes[i] == Kn * Kn) transitions = (const float*)d_in[i];
        else if (in_sizes[i] == Bn * Tn * Kn) inputs = (const float*)d_in[i];
    }
    if (!inputs) inputs = (const float*)d_in[0];
    if (!transitions) transitions = (const float*)d_in[1];

    float* out = (float*)d_out;

    // Static (~33.5 KB) + 16 KB dynamic -> opt in (host config, capture-safe).
    cudaFuncSetAttribute(viterbi_kernel,
                         cudaFuncAttributeMaxDynamicSharedMemorySize,
                         Kn * 32 * (int)sizeof(float2));

    seqlen_kernel<<<Bn, 256>>>(inputs);
    viterbi_kernel<<<Bn, 32, Kn * 32 * sizeof(float2)>>>(inputs, transitions, out);
}

// round 14
// speedup vs baseline: 2.4566x; 2.4566x over previous
#include <cuda_runtime.h>
#include <cfloat>

#define Bn 512
#define Tn 512
#define Kn 64
#define PD 8  // potentials prefetch ring depth (registers)

// Monotone float <-> uint order-preserving map (finite floats).
__device__ __forceinline__ unsigned fmap(float f) {
    const int i = __float_as_int(f);
    return (unsigned)(i ^ ((i >> 31) | 0x80000000));
}
__device__ __forceinline__ float funmap(unsigned u) {
    const int s = ~((int)u >> 31);
    return __int_as_float((int)(u ^ (0x80000000u | (unsigned)s)));
}

// ---------------------------------------------------------------------------
// Exact full 64-candidate scan (redo / general path). First max wins.
// ---------------------------------------------------------------------------
__device__ __noinline__ void full_scan64(
    float a_lo, float a_hi, const float2* trans2, int l,
    float& best0, float& best1, int& bi0, int& bi1)
{
    float b0 = -FLT_MAX, b1 = -FLT_MAX;
    int x0 = 0, x1 = 0;
#pragma unroll 4
    for (int i = 0; i < Kn; i++) {
        const float asel = (i < 32) ? a_lo : a_hi;
        const float av = __shfl_sync(0xffffffffu, asel, i & 31);
        const float2 tv = trans2[i * 32 + l];
        const float s0 = av + tv.x, s1 = av + tv.y;
        const bool g0 = s0 > b0; b0 = g0 ? s0 : b0; x0 = g0 ? i : x0;
        const bool g1 = s1 > b1; b1 = g1 ? s1 : b1; x1 = g1 ? i : x1;
    }
    best0 = b0; best1 = b1; bi0 = x0; bi1 = x1;
}

// Candidate fetch: alpha[i] via shuffle (uniform lane), trans column pair.
#define FETCH(i_, s0_, s1_)                                                 \
    {                                                                       \
        const float asel_ = ((i_) < 32) ? a_lo : a_hi;                      \
        const float av_ = __shfl_sync(0xffffffffu, asel_, (i_) & 31);       \
        const float2 tv_ = trans2[(i_) * 32 + l];                           \
        s0_ = av_ + tv_.x;                                                  \
        s1_ = av_ + tv_.y;                                                  \
    }

// One DP step (speculative fast path). Ring slot S_ is compile-time.
// Split-half 32-bit extraction (two parallel 2-deep ffs chains) replaces the
// serial 4-deep 64-bit chain. Slot0 always holds the smallest candidate tag
// and recovery applies it last -> jnp.argmax first-max bit-exact. Rare
// overflow candidates handled by an index-aware exact loop.
#define STEP_F(T_, S_)                                                       \
    {                                                                        \
        const int t_ = (T_);                                                 \
        const float p_lo = plo[S_];                                          \
        const float p_hi = phi[S_];                                          \
        {                                                                    \
            const int tp_ = t_ + PD;                                         \
            const int tl_ = (tp_ <= Tn - 1) ? tp_ : (Tn - 1);                \
            const float nl_ = pb[tl_ * Kn + l];                              \
            const float nh_ = pb[tl_ * Kn + 32 + l];                         \
            plo[S_] = nl_;                                                   \
            phi[S_] = nh_;                                                   \
            if (tp_ <= Tn - 1)  /* count each row exactly once */            \
                cnt += (int)(nl_ != 0.0f) + (int)(nh_ != 0.0f);              \
        }                                                                    \
        /* two PARALLEL 32-bit extraction chains (lo and hi halves) */       \
        int lo0 = __ffs((int)m_lo) - 1;                                      \
        const unsigned mlo2 = m_lo & (m_lo - 1);                             \
        int lo1 = mlo2 ? (__ffs((int)mlo2) - 1) : lo0;                       \
        unsigned mrest_lo = mlo2 & (mlo2 - 1);                               \
        int hi0 = m_hi ? (__ffs((int)m_hi) + 31) : -1;                       \
        const unsigned mhi2 = m_hi & (m_hi - 1);                             \
        int hi1 = mhi2 ? (__ffs((int)mhi2) + 31) : hi0;                      \
        unsigned mrest_hi = mhi2 & (mhi2 - 1);                               \
        if (!m_lo) { lo0 = hi0; lo1 = hi0; }  /* pad: dup smallest valid */  \
        if (!m_hi) { hi0 = lo0; hi1 = lo0; }  /* (both-empty impossible) */  \
        float sa0, sb0, sa1, sb1, sa2, sb2, sa3, sb3;                        \
        FETCH(lo0, sa0, sb0); FETCH(lo1, sa1, sb1);                          \
        FETCH(hi0, sa2, sb2); FETCH(hi1, sa3, sb3);                          \
        /* FMNMX tree: best is bitwise one of the candidates */              \
        float best0 = fmaxf(fmaxf(sa0, sa1), fmaxf(sa2, sa3));               \
        float best1 = fmaxf(fmaxf(sb0, sb1), fmaxf(sb2, sb3));               \
        /* recovery: descending slots, slot0 (smallest tag) applied last */  \
        int bi0 = hi1, bi1 = hi1;                                            \
        bi0 = (sa2 == best0) ? hi0 : bi0;  bi1 = (sb2 == best1) ? hi0 : bi1; \
        bi0 = (sa1 == best0) ? lo1 : bi0;  bi1 = (sb1 == best1) ? lo1 : bi1; \
        bi0 = (sa0 == best0) ? lo0 : bi0;  bi1 = (sb0 == best1) ? lo0 : bi1; \
        if (mrest_lo | mrest_hi) { /* rare: exact, index-aware tie-break */  \
            while (mrest_lo) {                                               \
                const int i_ = __ffs((int)mrest_lo) - 1;                     \
                mrest_lo &= mrest_lo - 1;                                    \
                float s0_, s1_;                                              \
                FETCH(i_, s0_, s1_);                                         \
                { const bool g = (s0_ > best0) ||                            \
                                 (s0_ == best0 && i_ < bi0);                 \
                  best0 = g ? s0_ : best0;  bi0 = g ? i_ : bi0; }            \
                { const bool g = (s1_ > best1) ||                            \
                                 (s1_ == best1 && i_ < bi1);                 \
                  best1 = g ? s1_ : best1;  bi1 = g ? i_ : bi1; }            \
            }                                                                \
            while (mrest_hi) {                                               \
                const int i_ = __ffs((int)mrest_hi) + 31;                    \
                mrest_hi &= mrest_hi - 1;                                    \
                float s0_, s1_;                                              \
                FETCH(i_, s0_, s1_);                                         \
                { const bool g = (s0_ > best0) ||                            \
                                 (s0_ == best0 && i_ < bi0);                 \
                  best0 = g ? s0_ : best0;  bi0 = g ? i_ : bi0; }            \
                { const bool g = (s1_ > best1) ||                            \
                                 (s1_ == best1 && i_ < bi1);                 \
                  best1 = g ? s1_ : best1;  bi1 = g ? i_ : bi1; }            \
            }                                                                \
        }                                                                    \
        a_lo = p_lo + best0;                                                 \
        a_hi = p_hi + best1;                                                 \
        bp[(t_ - 1) * Kn + l] = (unsigned char)bi0;                          \
        bp[(t_ - 1) * Kn + 32 + l] = (unsigned char)bi1;                     \
        /* EXACT threshold for the next step (proven R8 form) */             \
        const unsigned am_ = fmap(a_lo), ah_ = fmap(a_hi);                   \
        const unsigned wm_ =                                                 \
            __reduce_max_sync(0xffffffffu, am_ > ah_ ? am_ : ah_);           \
        const float thr_ = funmap(wm_) - rTp;                                \
        m_lo = __ballot_sync(0xffffffffu, a_lo >= thr_);                     \
        m_hi = __ballot_sync(0xffffffffu, a_hi >= thr_);                     \
    }

// ---------------------------------------------------------------------------
// Single-warp Viterbi with exact-threshold pruning + fused seq-len count.
// The prefetch ring touches every element of the batch exactly once, so the
// nonzero count (-> seq_len) is accumulated for free; if sl < Tn (never for
// this data, but required for exactness), the DP is redone in general mode.
// ---------------------------------------------------------------------------
__global__ __launch_bounds__(32) void viterbi_kernel(
    const float* __restrict__ pots,   // [B, T, K]
    const float* __restrict__ trans,  // [K, K]
    float* __restrict__ out)          // [B, T] float32
{
    extern __shared__ float2 trans2[];            // [64][32]: (T[i][l], T[i][l+32])
    __shared__ unsigned char bp[(Tn - 1) * Kn];   // 32704 B
    __shared__ unsigned char tags[Tn];
    __shared__ float alpha_f[Kn];

    const int b = blockIdx.x;
    const int l = threadIdx.x;  // lane; owns to-tags l and l+32

    // ---- Prologue: stage transitions (float2-packed) + padded range ----
    const float4* tr4 = (const float4*)trans;
    float tmin = FLT_MAX, tmax = -FLT_MAX;
#pragma unroll
    for (int q = 0; q < 32; q++) {
        const int idx = q * 32 + l;
        const float4 v = tr4[idx];
        tmin = fminf(tmin, fminf(fminf(v.x, v.y), fminf(v.z, v.w)));
        tmax = fmaxf(tmax, fmaxf(fmaxf(v.x, v.y), fmaxf(v.z, v.w)));
        const int base = idx * 4;
        const int i = base >> 6;
        const int c = base & 63;
        if (c < 32) {
            trans2[i * 32 + c + 0].x = v.x;
            trans2[i * 32 + c + 1].x = v.y;
            trans2[i * 32 + c + 2].x = v.z;
            trans2[i * 32 + c + 3].x = v.w;
        } else {
            const int cc = c - 32;
            trans2[i * 32 + cc + 0].y = v.x;
            trans2[i * 32 + cc + 1].y = v.y;
            trans2[i * 32 + cc + 2].y = v.z;
            trans2[i * 32 + cc + 3].y = v.w;
        }
    }
    const unsigned rmn = __reduce_min_sync(0xffffffffu, fmap(tmin));
    const unsigned rmx = __reduce_max_sync(0xffffffffu, fmap(tmax));
    const float r = funmap(rmx) - funmap(rmn);
    const float rTp = r + fabsf(r) * 1e-5f + 0.01f;  // pad only ADDS candidates
    __syncwarp();

    const float* pb = pots + (size_t)b * Tn * Kn;
    int cnt = 0;  // per-lane nonzero count (rows each touched exactly once)

    float a_lo = pb[l];
    float a_hi = pb[32 + l];
    cnt += (int)(a_lo != 0.0f) + (int)(a_hi != 0.0f);  // row 0

    // ---------------- SPECULATIVE FAST PATH (assume sl == Tn) --------------
    unsigned m_lo, m_hi;
    {
        const unsigned am = fmap(a_lo), ah = fmap(a_hi);
        const unsigned wm = __reduce_max_sync(0xffffffffu, am > ah ? am : ah);
        const float thr = funmap(wm) - rTp;
        m_lo = __ballot_sync(0xffffffffu, a_lo >= thr);
        m_hi = __ballot_sync(0xffffffffu, a_hi >= thr);
    }
    float plo[PD], phi[PD];
#pragma unroll
    for (int d = 1; d <= PD; d++) {  // rows 1..PD counted here
        const float nl = pb[d * Kn + l];
        const float nh = pb[d * Kn + 32 + l];
        plo[d & (PD - 1)] = nl;
        phi[d & (PD - 1)] = nh;
        cnt += (int)(nl != 0.0f) + (int)(nh != 0.0f);
    }
    {
        int t = 1;
#pragma unroll 1
        for (int tb = 0; tb < 63; tb++) {
            STEP_F(t + 0, 1); STEP_F(t + 1, 2); STEP_F(t + 2, 3); STEP_F(t + 3, 4);
            STEP_F(t + 4, 5); STEP_F(t + 5, 6); STEP_F(t + 6, 7); STEP_F(t + 7, 0);
            t += 8;
        }
        STEP_F(t + 0, 1); STEP_F(t + 1, 2); STEP_F(t + 2, 3); STEP_F(t + 3, 4);
        STEP_F(t + 4, 5); STEP_F(t + 5, 6); STEP_F(t + 6, 7);
    }

    // ---- Verify speculation: exact seq_len from the fused count ----
    const int total = __reduce_add_sync(0xffffffffu, cnt);
    const int sl = total >> 6;  // floor(mean over K=64), exact

    if (sl < Tn) {
        // -------- RARE EXACT REDO: general path with mask semantics --------
        a_lo = pb[l];
        a_hi = pb[32 + l];
#pragma unroll 1
        for (int t = 1; t < Tn; t++) {
            if (t < sl) {
                float best0, best1; int bi0, bi1;
                full_scan64(a_lo, a_hi, trans2, l, best0, best1, bi0, bi1);
                a_lo = pb[t * Kn + l] + best0;
                a_hi = pb[t * Kn + 32 + l] + best1;
                bp[(t - 1) * Kn + l] = (unsigned char)bi0;
                bp[(t - 1) * Kn + 32 + l] = (unsigned char)bi1;
            } else {
                bp[(t - 1) * Kn + l] = (unsigned char)l;
                bp[(t - 1) * Kn + 32 + l] = (unsigned char)(32 + l);
            }
        }
    }

    // Final alpha -> smem for the backtrace scan
    alpha_f[l] = a_lo;
    alpha_f[32 + l] = a_hi;
    __syncwarp();

    // Backtrace (smem pointer-chase) by lane 0. First max wins.
    if (l == 0) {
        float bv = alpha_f[0];
        int bt = 0;
#pragma unroll 1
        for (int i = 1; i < Kn; i++) {
            const float v = alpha_f[i];
            if (v > bv) { bv = v; bt = i; }
        }
        int tg = bt;
        tags[Tn - 1] = (unsigned char)tg;
#pragma unroll 1
        for (int tt = Tn - 2; tt >= 0; tt--) {
            tg = bp[tt * Kn + tg];
            tags[tt] = (unsigned char)tg;
        }
    }
    __syncwarp();

    // Coalesced float32 output write (16 per lane).
    float* ob = out + (size_t)b * Tn;
#pragma unroll
    for (int tt = l; tt < Tn; tt += 32) ob[tt] = (float)tags[tt];
}

// ---------------------------------------------------------------------------
extern "C" void kernel_launch(void* const* d_in, const int* in_sizes, int n_in,
                              void* d_out, int out_size) {
    const float* inputs = nullptr;
    const float* transitions = nullptr;
    for (int i = 0; i < n_in; i++) {
        if (in_sizes[i] == Kn * Kn) transitions = (const float*)d_in[i];
        else if (in_sizes[i] == Bn * Tn * Kn) inputs = (const float*)d_in[i];
    }
    if (!inputs) inputs = (const float*)d_in[0];
    if (!transitions) transitions = (const float*)d_in[1];

    float* out = (float*)d_out;

    // Static (~33.5 KB) + 16 KB dynamic -> opt in (host config, capture-safe).
    cudaFuncSetAttribute(viterbi_kernel,
                         cudaFuncAttributeMaxDynamicSharedMemorySize,
                         Kn * 32 * (int)sizeof(float2));

    viterbi_kernel<<<Bn, 32, Kn * 32 * sizeof(float2)>>>(inputs, transitions, out);
}